// round 11
// baseline (speedup 1.0000x reference)
#include <cuda_runtime.h>
#include <cuda_fp16.h>

#define NMAX  100000
#define EMAX  1600000
#define D_IN  128
#define D_OUT 32
#define CAP   80          // max edges per row bin (binomial mean 16; P(deg>80)~0)

__device__ __half g_hh[NMAX * D_OUT];
__device__ float  g_w2[NMAX];
__device__ int    g_cnt[NMAX];
__device__ unsigned long long g_bins[(size_t)NMAX * CAP];

__device__ __forceinline__ unsigned long long fma2(
    unsigned long long a, unsigned long long b, unsigned long long c)
{
    unsigned long long d;
    asm("fma.rn.f32x2 %0, %1, %2, %3;" : "=l"(d) : "l"(a), "l"(b), "l"(c));
    return d;
}

__device__ __forceinline__ unsigned long long pack2(float x)
{
    unsigned long long d;
    asm("mov.b64 %0, {%1, %1};" : "=l"(d) : "f"(x));
    return d;
}

// ---------------------------------------------------------------------------
// Kernel A: h = relu(X @ W) in fp16 + w2 precompute.
// __launch_bounds__(256, 2): hard cap at 2 blocks/SM (40K regs) so 3 bin
// blocks (3 x 8K regs) ALWAYS fit alongside -> forced co-scheduling.
// ---------------------------------------------------------------------------
__global__ __launch_bounds__(256, 2) void gemm_relu_kernel(
    const float* __restrict__ X, const float* __restrict__ W,
    const int* __restrict__ arrive, const float* __restrict__ dw2,
    const int* __restrict__ obs_ptr, int n)
{
    __shared__ float Xs[32 * 128];
    __shared__ float Ws[128 * 32];

    const int tid = threadIdx.x;
    const int rowbase = blockIdx.x * 128;

    if (tid < 128) {
        const int node = rowbase + tid;
        if (node < n) {
            const int obs = obs_ptr ? __ldg(obs_ptr) : 60;
            const int idx = 60 * obs - __ldg(arrive + node) - 1;
            g_w2[node] = __ldg(dw2 + idx);
        }
    }

    const float4* X4 = reinterpret_cast<const float4*>(X);
    const int lc = tid & 7;

    float4 pf[4];
    #pragma unroll
    for (int s = 0; s < 4; s++) {
        const int rr = (s * 256 + tid) >> 3;
        float4 v = make_float4(0.f, 0.f, 0.f, 0.f);
        if (rowbase + rr < n) v = X4[(size_t)(rowbase + rr) * 32 + lc];
        pf[s] = v;
    }

    const float4* W4 = reinterpret_cast<const float4*>(W);
    float4* Ws4 = reinterpret_cast<float4*>(Ws);
    #pragma unroll
    for (int i = tid; i < 1024; i += 256) Ws4[i] = W4[i];

    const int rowgrp = tid >> 3;
    const int c0 = (tid & 7) * 4;

    unsigned long long acc[2][4];
    #pragma unroll
    for (int rp = 0; rp < 2; rp++)
        #pragma unroll
        for (int j = 0; j < 4; j++) acc[rp][j] = 0ULL;

    #pragma unroll 1
    for (int chunk = 0; chunk < 4; chunk++) {
        #pragma unroll
        for (int s = 0; s < 4; s++) {
            const int rr = (s * 256 + tid) >> 3;
            const int base = 4 * ((rr >> 2) ^ lc) + (rr & 3);
            Xs[(4 * lc + 0) * 128 + base] = pf[s].x;
            Xs[(4 * lc + 1) * 128 + base] = pf[s].y;
            Xs[(4 * lc + 2) * 128 + base] = pf[s].z;
            Xs[(4 * lc + 3) * 128 + base] = pf[s].w;
        }
        __syncthreads();

        if (chunk < 3) {
            #pragma unroll
            for (int s = 0; s < 4; s++) {
                const int rr = (s * 256 + tid) >> 3;
                float4 v = make_float4(0.f, 0.f, 0.f, 0.f);
                if (rowbase + rr < n)
                    v = X4[(size_t)(rowbase + rr) * 32 + (chunk + 1) * 8 + lc];
                pf[s] = v;
            }
        }

        #pragma unroll 4
        for (int kl = 0; kl < 32; kl++) {
            const int m = (kl >> 2) & 7;
            const ulonglong2 x2 = *reinterpret_cast<const ulonglong2*>(
                &Xs[kl * 128 + ((rowgrp ^ m) << 2)]);

            const int kg = chunk * 32 + kl;
            const float4 w = *reinterpret_cast<const float4*>(&Ws[kg * 32 + c0]);
            const unsigned long long wp0 = pack2(w.x);
            const unsigned long long wp1 = pack2(w.y);
            const unsigned long long wp2 = pack2(w.z);
            const unsigned long long wp3 = pack2(w.w);

            acc[0][0] = fma2(x2.x, wp0, acc[0][0]);
            acc[0][1] = fma2(x2.x, wp1, acc[0][1]);
            acc[0][2] = fma2(x2.x, wp2, acc[0][2]);
            acc[0][3] = fma2(x2.x, wp3, acc[0][3]);
            acc[1][0] = fma2(x2.y, wp0, acc[1][0]);
            acc[1][1] = fma2(x2.y, wp1, acc[1][1]);
            acc[1][2] = fma2(x2.y, wp2, acc[1][2]);
            acc[1][3] = fma2(x2.y, wp3, acc[1][3]);
        }
        __syncthreads();
    }

    #pragma unroll
    for (int rp = 0; rp < 2; rp++) {
        float lo[4], hi[4];
        #pragma unroll
        for (int j = 0; j < 4; j++) {
            float l, h;
            asm("mov.b64 {%0, %1}, %2;" : "=f"(l), "=f"(h) : "l"(acc[rp][j]));
            lo[j] = fmaxf(l, 0.f);
            hi[j] = fmaxf(h, 0.f);
        }
        const int grl = rowbase + rowgrp * 4 + 2 * rp;
        if (grl < n) {
            const __half2 a = __floats2half2_rn(lo[0], lo[1]);
            const __half2 b = __floats2half2_rn(lo[2], lo[3]);
            uint2 u;
            u.x = *reinterpret_cast<const unsigned*>(&a);
            u.y = *reinterpret_cast<const unsigned*>(&b);
            *reinterpret_cast<uint2*>(&g_hh[grl * D_OUT + c0]) = u;
        }
        if (grl + 1 < n) {
            const __half2 a = __floats2half2_rn(hi[0], hi[1]);
            const __half2 b = __floats2half2_rn(hi[2], hi[3]);
            uint2 u;
            u.x = *reinterpret_cast<const unsigned*>(&a);
            u.y = *reinterpret_cast<const unsigned*>(&b);
            *reinterpret_cast<uint2*>(&g_hh[(grl + 1) * D_OUT + c0]) = u;
        }
    }
}

// ---------------------------------------------------------------------------
// Kernel B: bin edges, GRID-STRIDE with small grid (3 blocks/SM) so it
// co-resides with the GEMM and fills its issue/LSU gaps.
// slot = row*CAP + atomicAdd(cnt[row],1); payload = (col | dw1[time]<<32).
// ---------------------------------------------------------------------------
__global__ __launch_bounds__(256) void bin_kernel(
    const int* __restrict__ erow, const int* __restrict__ ecol,
    const int* __restrict__ etime, const float* __restrict__ dw1, int E)
{
    const int nquad = E >> 2;
    const int stride = gridDim.x * 256;

    for (int i = blockIdx.x * 256 + threadIdx.x; i < nquad; i += stride) {
        const int4 r  = reinterpret_cast<const int4*>(erow)[i];
        const int4 c  = reinterpret_cast<const int4*>(ecol)[i];
        const int4 tt = reinterpret_cast<const int4*>(etime)[i];
        const unsigned long long pl0 = (unsigned)c.x |
            ((unsigned long long)__float_as_uint(__ldg(dw1 + tt.x)) << 32);
        const unsigned long long pl1 = (unsigned)c.y |
            ((unsigned long long)__float_as_uint(__ldg(dw1 + tt.y)) << 32);
        const unsigned long long pl2 = (unsigned)c.z |
            ((unsigned long long)__float_as_uint(__ldg(dw1 + tt.z)) << 32);
        const unsigned long long pl3 = (unsigned)c.w |
            ((unsigned long long)__float_as_uint(__ldg(dw1 + tt.w)) << 32);
        const int p0 = atomicAdd(&g_cnt[r.x], 1);
        const int p1 = atomicAdd(&g_cnt[r.y], 1);
        const int p2 = atomicAdd(&g_cnt[r.z], 1);
        const int p3 = atomicAdd(&g_cnt[r.w], 1);
        if (p0 < CAP) g_bins[(size_t)r.x * CAP + p0] = pl0;
        if (p1 < CAP) g_bins[(size_t)r.y * CAP + p1] = pl1;
        if (p2 < CAP) g_bins[(size_t)r.z * CAP + p2] = pl2;
        if (p3 < CAP) g_bins[(size_t)r.w * CAP + p3] = pl3;
    }

    if (blockIdx.x == 0 && threadIdx.x == 0) {
        for (int e = nquad << 2; e < E; e++) {
            const int r = erow[e];
            const unsigned long long pl = (unsigned)ecol[e] |
                ((unsigned long long)__float_as_uint(__ldg(dw1 + etime[e])) << 32);
            const int p = atomicAdd(&g_cnt[r], 1);
            if (p < CAP) g_bins[(size_t)r * CAP + p] = pl;
        }
    }
}

// ---------------------------------------------------------------------------
// Kernel C: gather (fp16 h), no atomics. 8 lanes/row, 4-wide unroll.
// out[r] = w2[r] * sum_i d_i * h[c_i]
// ---------------------------------------------------------------------------
__global__ __launch_bounds__(256) void gather_kernel(float* __restrict__ out, int n)
{
    const int gid = blockIdx.x * 256 + threadIdx.x;
    const int r = gid >> 3;
    const int p = gid & 7;
    if (r >= n) return;

    int deg = __ldg(&g_cnt[r]);
    if (deg > CAP) deg = CAP;
    const unsigned long long* bin = &g_bins[(size_t)r * CAP];

    float a0 = 0.f, a1 = 0.f, a2 = 0.f, a3 = 0.f;

    int i = 0;
    for (; i + 3 < deg; i += 4) {
        const unsigned long long pk0 = __ldg(&bin[i]);
        const unsigned long long pk1 = __ldg(&bin[i + 1]);
        const unsigned long long pk2 = __ldg(&bin[i + 2]);
        const unsigned long long pk3 = __ldg(&bin[i + 3]);
        const uint2 u0 = *reinterpret_cast<const uint2*>(
            &g_hh[(unsigned)pk0 * D_OUT + p * 4]);
        const uint2 u1 = *reinterpret_cast<const uint2*>(
            &g_hh[(unsigned)pk1 * D_OUT + p * 4]);
        const uint2 u2 = *reinterpret_cast<const uint2*>(
            &g_hh[(unsigned)pk2 * D_OUT + p * 4]);
        const uint2 u3 = *reinterpret_cast<const uint2*>(
            &g_hh[(unsigned)pk3 * D_OUT + p * 4]);
        const float d0 = __uint_as_float((unsigned)(pk0 >> 32));
        const float d1 = __uint_as_float((unsigned)(pk1 >> 32));
        const float d2 = __uint_as_float((unsigned)(pk2 >> 32));
        const float d3 = __uint_as_float((unsigned)(pk3 >> 32));
        {
            const float2 f01 = __half22float2(*reinterpret_cast<const __half2*>(&u0.x));
            const float2 f23 = __half22float2(*reinterpret_cast<const __half2*>(&u0.y));
            a0 = fmaf(d0, f01.x, a0); a1 = fmaf(d0, f01.y, a1);
            a2 = fmaf(d0, f23.x, a2); a3 = fmaf(d0, f23.y, a3);
        }
        {
            const float2 f01 = __half22float2(*reinterpret_cast<const __half2*>(&u1.x));
            const float2 f23 = __half22float2(*reinterpret_cast<const __half2*>(&u1.y));
            a0 = fmaf(d1, f01.x, a0); a1 = fmaf(d1, f01.y, a1);
            a2 = fmaf(d1, f23.x, a2); a3 = fmaf(d1, f23.y, a3);
        }
        {
            const float2 f01 = __half22float2(*reinterpret_cast<const __half2*>(&u2.x));
            const float2 f23 = __half22float2(*reinterpret_cast<const __half2*>(&u2.y));
            a0 = fmaf(d2, f01.x, a0); a1 = fmaf(d2, f01.y, a1);
            a2 = fmaf(d2, f23.x, a2); a3 = fmaf(d2, f23.y, a3);
        }
        {
            const float2 f01 = __half22float2(*reinterpret_cast<const __half2*>(&u3.x));
            const float2 f23 = __half22float2(*reinterpret_cast<const __half2*>(&u3.y));
            a0 = fmaf(d3, f01.x, a0); a1 = fmaf(d3, f01.y, a1);
            a2 = fmaf(d3, f23.x, a2); a3 = fmaf(d3, f23.y, a3);
        }
    }
    for (; i < deg; i++) {
        const unsigned long long pk = __ldg(&bin[i]);
        const float d = __uint_as_float((unsigned)(pk >> 32));
        const uint2 u = *reinterpret_cast<const uint2*>(
            &g_hh[(unsigned)pk * D_OUT + p * 4]);
        const float2 f01 = __half22float2(*reinterpret_cast<const __half2*>(&u.x));
        const float2 f23 = __half22float2(*reinterpret_cast<const __half2*>(&u.y));
        a0 = fmaf(d, f01.x, a0); a1 = fmaf(d, f01.y, a1);
        a2 = fmaf(d, f23.x, a2); a3 = fmaf(d, f23.y, a3);
    }

    const float w = __ldg(&g_w2[r]);
    *reinterpret_cast<float4*>(&out[r * D_OUT + p * 4]) =
        make_float4(a0 * w, a1 * w, a2 * w, a3 * w);
}

// ---------------------------------------------------------------------------
// Launch: GEMM first (2 blocks/SM hard cap), then small-grid bin co-resides
// in the leftover 24K regs / 48 warp slots per SM. Join -> gather.
// ---------------------------------------------------------------------------
extern "C" void kernel_launch(void* const* d_in, const int* in_sizes, int n_in,
                              void* d_out, int out_size)
{
    const float* X    = (const float*)d_in[0];
    const float* W    = (const float*)d_in[1];
    const float* dw1  = (const float*)d_in[2];
    const float* dw2  = (const float*)d_in[3];
    const int*  erow  = (const int*)d_in[4];
    const int*  ecol  = (const int*)d_in[5];
    const int*  etime = (const int*)d_in[6];
    const int*  arrive= (const int*)d_in[7];
    const int*  obs_p = (n_in > 8) ? (const int*)d_in[8] : nullptr;

    const int n = in_sizes[7];
    const int E = in_sizes[4];

    void* cnt_ptr = nullptr;
    cudaGetSymbolAddress(&cnt_ptr, g_cnt);

    cudaStream_t s2;
    cudaEvent_t evF, evJ;
    cudaStreamCreateWithFlags(&s2, cudaStreamNonBlocking);
    cudaEventCreateWithFlags(&evF, cudaEventDisableTiming);
    cudaEventCreateWithFlags(&evJ, cudaEventDisableTiming);

    cudaEventRecord(evF, 0);
    cudaStreamWaitEvent(s2, evF, 0);

    // ---- branch A on main stream: GEMM + w2 (launched FIRST) ----
    gemm_relu_kernel<<<(n + 127) / 128, 256>>>(X, W, arrive, dw2, obs_p, n);

    // ---- branch B on s2: zero counters + grid-stride bin (3 blocks/SM) ----
    cudaMemsetAsync(cnt_ptr, 0, (size_t)n * sizeof(int), s2);
    bin_kernel<<<444, 256, 0, s2>>>(erow, ecol, etime, dw1, E);
    cudaEventRecord(evJ, s2);

    // ---- join, then gather ----
    cudaStreamWaitEvent(0, evJ, 0);
    gather_kernel<<<(n * 8 + 255) / 256, 256>>>((float*)d_out, n);
}

// round 12
// speedup vs baseline: 1.0940x; 1.0940x over previous
#include <cuda_runtime.h>
#include <cuda_fp16.h>

#define NMAX  100000
#define EMAX  1600000
#define D_IN  128
#define D_OUT 32
#define CAP   80          // max edges per row bin (binomial mean 16; P(deg>80)~0)

__device__ __half g_hh[NMAX * D_OUT];
__device__ float  g_w2[NMAX];
__device__ int    g_cnt[NMAX];
__device__ unsigned long long g_bins[(size_t)NMAX * CAP];

__device__ __forceinline__ unsigned long long fma2(
    unsigned long long a, unsigned long long b, unsigned long long c)
{
    unsigned long long d;
    asm("fma.rn.f32x2 %0, %1, %2, %3;" : "=l"(d) : "l"(a), "l"(b), "l"(c));
    return d;
}

__device__ __forceinline__ unsigned long long pack2(float x)
{
    unsigned long long d;
    asm("mov.b64 %0, {%1, %1};" : "=l"(d) : "f"(x));
    return d;
}

// ---------------------------------------------------------------------------
// Kernel A: h = relu(X @ W) in fp16 + w2 precompute.
// 256 threads, 256-row tile, thread = 8 rows x 4 cols: per k-step a warp
// issues 3 LDS.128 per 16 FMA2 (vs 2 per 8 before) -> 25% less smem-port
// pressure (the measured binder). Register-prefetch pipeline on X.
// Xs transposed + swizzled: phys(k,r) = k*256 + 4*((r>>2)^(k>>2)) + (r&3).
// ---------------------------------------------------------------------------
__global__ __launch_bounds__(256, 2) void gemm_relu_kernel(
    const float* __restrict__ X, const float* __restrict__ W,
    const int* __restrict__ arrive, const float* __restrict__ dw2,
    const int* __restrict__ obs_ptr, int n)
{
    __shared__ float Xs[32 * 256];    // 32 KB
    __shared__ float Ws[128 * 32];    // 16 KB

    const int tid = threadIdx.x;
    const int rowbase = blockIdx.x * 256;

    // per-node w2 = dw2[60*obs - arrive - 1]
    {
        const int node = rowbase + tid;
        if (node < n) {
            const int obs = obs_ptr ? __ldg(obs_ptr) : 60;
            const int idx = 60 * obs - __ldg(arrive + node) - 1;
            g_w2[node] = __ldg(dw2 + idx);
        }
    }

    const float4* X4 = reinterpret_cast<const float4*>(X);
    const int lc = tid & 7;               // loader k-float4 within chunk

    // prefetch chunk 0: 8 float4 per thread (rows (s*256+tid)>>3)
    float4 pf[8];
    #pragma unroll
    for (int s = 0; s < 8; s++) {
        const int r = (s * 256 + tid) >> 3;          // 0..255
        float4 v = make_float4(0.f, 0.f, 0.f, 0.f);
        if (rowbase + r < n) v = X4[(size_t)(rowbase + r) * 32 + lc];
        pf[s] = v;
    }

    // load W (coalesced float4)
    const float4* W4 = reinterpret_cast<const float4*>(W);
    float4* Ws4 = reinterpret_cast<float4*>(Ws);
    #pragma unroll
    for (int i = tid; i < 1024; i += 256) Ws4[i] = W4[i];

    const int rowgrp = tid >> 3;          // 0..31 -> rows 8rg..8rg+7
    const int c0 = (tid & 7) * 4;         // cols c0..c0+3
    const int b0 = rowgrp * 2;            // 4-row block index

    unsigned long long acc[4][4];         // [row-pair][col]
    #pragma unroll
    for (int rp = 0; rp < 4; rp++)
        #pragma unroll
        for (int j = 0; j < 4; j++) acc[rp][j] = 0ULL;

    #pragma unroll 1
    for (int chunk = 0; chunk < 4; chunk++) {
        // store prefetched tile (transposed + swizzled)
        #pragma unroll
        for (int s = 0; s < 8; s++) {
            const int r = (s * 256 + tid) >> 3;
            const int base = 4 * ((r >> 2) ^ lc) + (r & 3);
            Xs[(4 * lc + 0) * 256 + base] = pf[s].x;
            Xs[(4 * lc + 1) * 256 + base] = pf[s].y;
            Xs[(4 * lc + 2) * 256 + base] = pf[s].z;
            Xs[(4 * lc + 3) * 256 + base] = pf[s].w;
        }
        __syncthreads();

        // prefetch next chunk (overlaps compute)
        if (chunk < 3) {
            #pragma unroll
            for (int s = 0; s < 8; s++) {
                const int r = (s * 256 + tid) >> 3;
                float4 v = make_float4(0.f, 0.f, 0.f, 0.f);
                if (rowbase + r < n)
                    v = X4[(size_t)(rowbase + r) * 32 + (chunk + 1) * 8 + lc];
                pf[s] = v;
            }
        }

        // compute 32 k-steps
        #pragma unroll 4
        for (int kl = 0; kl < 32; kl++) {
            const int m = kl >> 2;
            const ulonglong2 pa = *reinterpret_cast<const ulonglong2*>(
                &Xs[kl * 256 + (((b0)     ^ m) << 2)]);   // rows 8rg..8rg+3
            const ulonglong2 pb = *reinterpret_cast<const ulonglong2*>(
                &Xs[kl * 256 + (((b0 + 1) ^ m) << 2)]);   // rows 8rg+4..+7

            const int kg = chunk * 32 + kl;
            const float4 w = *reinterpret_cast<const float4*>(&Ws[kg * 32 + c0]);
            const unsigned long long wp0 = pack2(w.x);
            const unsigned long long wp1 = pack2(w.y);
            const unsigned long long wp2 = pack2(w.z);
            const unsigned long long wp3 = pack2(w.w);

            acc[0][0] = fma2(pa.x, wp0, acc[0][0]);
            acc[0][1] = fma2(pa.x, wp1, acc[0][1]);
            acc[0][2] = fma2(pa.x, wp2, acc[0][2]);
            acc[0][3] = fma2(pa.x, wp3, acc[0][3]);
            acc[1][0] = fma2(pa.y, wp0, acc[1][0]);
            acc[1][1] = fma2(pa.y, wp1, acc[1][1]);
            acc[1][2] = fma2(pa.y, wp2, acc[1][2]);
            acc[1][3] = fma2(pa.y, wp3, acc[1][3]);
            acc[2][0] = fma2(pb.x, wp0, acc[2][0]);
            acc[2][1] = fma2(pb.x, wp1, acc[2][1]);
            acc[2][2] = fma2(pb.x, wp2, acc[2][2]);
            acc[2][3] = fma2(pb.x, wp3, acc[2][3]);
            acc[3][0] = fma2(pb.y, wp0, acc[3][0]);
            acc[3][1] = fma2(pb.y, wp1, acc[3][1]);
            acc[3][2] = fma2(pb.y, wp2, acc[3][2]);
            acc[3][3] = fma2(pb.y, wp3, acc[3][3]);
        }
        __syncthreads();
    }

    // epilogue: unpack, relu, fp16 store (8 rows x 4 cols)
    #pragma unroll
    for (int rp = 0; rp < 4; rp++) {
        float lo[4], hi[4];
        #pragma unroll
        for (int j = 0; j < 4; j++) {
            float l, h;
            asm("mov.b64 {%0, %1}, %2;" : "=f"(l), "=f"(h) : "l"(acc[rp][j]));
            lo[j] = fmaxf(l, 0.f);
            hi[j] = fmaxf(h, 0.f);
        }
        const int grl = rowbase + rowgrp * 8 + 2 * rp;
        if (grl < n) {
            const __half2 a = __floats2half2_rn(lo[0], lo[1]);
            const __half2 b = __floats2half2_rn(lo[2], lo[3]);
            uint2 u;
            u.x = *reinterpret_cast<const unsigned*>(&a);
            u.y = *reinterpret_cast<const unsigned*>(&b);
            *reinterpret_cast<uint2*>(&g_hh[grl * D_OUT + c0]) = u;
        }
        if (grl + 1 < n) {
            const __half2 a = __floats2half2_rn(hi[0], hi[1]);
            const __half2 b = __floats2half2_rn(hi[2], hi[3]);
            uint2 u;
            u.x = *reinterpret_cast<const unsigned*>(&a);
            u.y = *reinterpret_cast<const unsigned*>(&b);
            *reinterpret_cast<uint2*>(&g_hh[(grl + 1) * D_OUT + c0]) = u;
        }
    }
}

// ---------------------------------------------------------------------------
// Kernel B: bin edges (R10-proven). slot = row*CAP + atomicAdd(cnt[row],1).
// ---------------------------------------------------------------------------
__global__ __launch_bounds__(256) void bin_kernel(
    const int* __restrict__ erow, const int* __restrict__ ecol,
    const int* __restrict__ etime, const float* __restrict__ dw1, int E)
{
    const int i = blockIdx.x * 256 + threadIdx.x;
    const int e0 = i * 4;
    if (e0 + 3 < E) {
        const int4 r  = reinterpret_cast<const int4*>(erow)[i];
        const int4 c  = reinterpret_cast<const int4*>(ecol)[i];
        const int4 tt = reinterpret_cast<const int4*>(etime)[i];
        const unsigned long long pl0 = (unsigned)c.x |
            ((unsigned long long)__float_as_uint(__ldg(dw1 + tt.x)) << 32);
        const unsigned long long pl1 = (unsigned)c.y |
            ((unsigned long long)__float_as_uint(__ldg(dw1 + tt.y)) << 32);
        const unsigned long long pl2 = (unsigned)c.z |
            ((unsigned long long)__float_as_uint(__ldg(dw1 + tt.z)) << 32);
        const unsigned long long pl3 = (unsigned)c.w |
            ((unsigned long long)__float_as_uint(__ldg(dw1 + tt.w)) << 32);
        const int p0 = atomicAdd(&g_cnt[r.x], 1);
        const int p1 = atomicAdd(&g_cnt[r.y], 1);
        const int p2 = atomicAdd(&g_cnt[r.z], 1);
        const int p3 = atomicAdd(&g_cnt[r.w], 1);
        if (p0 < CAP) g_bins[(size_t)r.x * CAP + p0] = pl0;
        if (p1 < CAP) g_bins[(size_t)r.y * CAP + p1] = pl1;
        if (p2 < CAP) g_bins[(size_t)r.z * CAP + p2] = pl2;
        if (p3 < CAP) g_bins[(size_t)r.w * CAP + p3] = pl3;
    } else if (e0 < E) {
        for (int e = e0; e < E; e++) {
            const int r = erow[e];
            const unsigned long long pl = (unsigned)ecol[e] |
                ((unsigned long long)__float_as_uint(__ldg(dw1 + etime[e])) << 32);
            const int p = atomicAdd(&g_cnt[r], 1);
            if (p < CAP) g_bins[(size_t)r * CAP + p] = pl;
        }
    }
}

// ---------------------------------------------------------------------------
// Kernel C: gather (fp16 h), no atomics. 8 lanes/row, 4-wide unroll.
// out[r] = w2[r] * sum_i d_i * h[c_i]
// ---------------------------------------------------------------------------
__global__ __launch_bounds__(256) void gather_kernel(float* __restrict__ out, int n)
{
    const int gid = blockIdx.x * 256 + threadIdx.x;
    const int r = gid >> 3;
    const int p = gid & 7;
    if (r >= n) return;

    int deg = __ldg(&g_cnt[r]);
    if (deg > CAP) deg = CAP;
    const unsigned long long* bin = &g_bins[(size_t)r * CAP];

    float a0 = 0.f, a1 = 0.f, a2 = 0.f, a3 = 0.f;

    int i = 0;
    for (; i + 3 < deg; i += 4) {
        const unsigned long long pk0 = __ldg(&bin[i]);
        const unsigned long long pk1 = __ldg(&bin[i + 1]);
        const unsigned long long pk2 = __ldg(&bin[i + 2]);
        const unsigned long long pk3 = __ldg(&bin[i + 3]);
        const uint2 u0 = *reinterpret_cast<const uint2*>(
            &g_hh[(unsigned)pk0 * D_OUT + p * 4]);
        const uint2 u1 = *reinterpret_cast<const uint2*>(
            &g_hh[(unsigned)pk1 * D_OUT + p * 4]);
        const uint2 u2 = *reinterpret_cast<const uint2*>(
            &g_hh[(unsigned)pk2 * D_OUT + p * 4]);
        const uint2 u3 = *reinterpret_cast<const uint2*>(
            &g_hh[(unsigned)pk3 * D_OUT + p * 4]);
        const float d0 = __uint_as_float((unsigned)(pk0 >> 32));
        const float d1 = __uint_as_float((unsigned)(pk1 >> 32));
        const float d2 = __uint_as_float((unsigned)(pk2 >> 32));
        const float d3 = __uint_as_float((unsigned)(pk3 >> 32));
        {
            const float2 f01 = __half22float2(*reinterpret_cast<const __half2*>(&u0.x));
            const float2 f23 = __half22float2(*reinterpret_cast<const __half2*>(&u0.y));
            a0 = fmaf(d0, f01.x, a0); a1 = fmaf(d0, f01.y, a1);
            a2 = fmaf(d0, f23.x, a2); a3 = fmaf(d0, f23.y, a3);
        }
        {
            const float2 f01 = __half22float2(*reinterpret_cast<const __half2*>(&u1.x));
            const float2 f23 = __half22float2(*reinterpret_cast<const __half2*>(&u1.y));
            a0 = fmaf(d1, f01.x, a0); a1 = fmaf(d1, f01.y, a1);
            a2 = fmaf(d1, f23.x, a2); a3 = fmaf(d1, f23.y, a3);
        }
        {
            const float2 f01 = __half22float2(*reinterpret_cast<const __half2*>(&u2.x));
            const float2 f23 = __half22float2(*reinterpret_cast<const __half2*>(&u2.y));
            a0 = fmaf(d2, f01.x, a0); a1 = fmaf(d2, f01.y, a1);
            a2 = fmaf(d2, f23.x, a2); a3 = fmaf(d2, f23.y, a3);
        }
        {
            const float2 f01 = __half22float2(*reinterpret_cast<const __half2*>(&u3.x));
            const float2 f23 = __half22float2(*reinterpret_cast<const __half2*>(&u3.y));
            a0 = fmaf(d3, f01.x, a0); a1 = fmaf(d3, f01.y, a1);
            a2 = fmaf(d3, f23.x, a2); a3 = fmaf(d3, f23.y, a3);
        }
    }
    for (; i < deg; i++) {
        const unsigned long long pk = __ldg(&bin[i]);
        const float d = __uint_as_float((unsigned)(pk >> 32));
        const uint2 u = *reinterpret_cast<const uint2*>(
            &g_hh[(unsigned)pk * D_OUT + p * 4]);
        const float2 f01 = __half22float2(*reinterpret_cast<const __half2*>(&u.x));
        const float2 f23 = __half22float2(*reinterpret_cast<const __half2*>(&u.y));
        a0 = fmaf(d, f01.x, a0); a1 = fmaf(d, f01.y, a1);
        a2 = fmaf(d, f23.x, a2); a3 = fmaf(d, f23.y, a3);
    }

    const float w = __ldg(&g_w2[r]);
    *reinterpret_cast<float4*>(&out[r * D_OUT + p * 4]) =
        make_float4(a0 * w, a1 * w, a2 * w, a3 * w);
}

// ---------------------------------------------------------------------------
// Launch: single stream (fork-join proven useless on this stack).
// ---------------------------------------------------------------------------
extern "C" void kernel_launch(void* const* d_in, const int* in_sizes, int n_in,
                              void* d_out, int out_size)
{
    const float* X    = (const float*)d_in[0];
    const float* W    = (const float*)d_in[1];
    const float* dw1  = (const float*)d_in[2];
    const float* dw2  = (const float*)d_in[3];
    const int*  erow  = (const int*)d_in[4];
    const int*  ecol  = (const int*)d_in[5];
    const int*  etime = (const int*)d_in[6];
    const int*  arrive= (const int*)d_in[7];
    const int*  obs_p = (n_in > 8) ? (const int*)d_in[8] : nullptr;

    const int n = in_sizes[7];
    const int E = in_sizes[4];

    void* cnt_ptr = nullptr;
    cudaGetSymbolAddress(&cnt_ptr, g_cnt);
    cudaMemsetAsync(cnt_ptr, 0, (size_t)n * sizeof(int));

    bin_kernel<<<(E / 4 + 255) / 256 + 1, 256>>>(erow, ecol, etime, dw1, E);
    gemm_relu_kernel<<<(n + 255) / 256, 256>>>(X, W, arrive, dw2, obs_p, n);
    gather_kernel<<<(n * 8 + 255) / 256, 256>>>((float*)d_out, n);
}

// round 13
// speedup vs baseline: 1.0955x; 1.0014x over previous
#include <cuda_runtime.h>
#include <cuda_fp16.h>

#define NMAX  100000
#define EMAX  1600000
#define D_IN  128
#define D_OUT 32
#define CAP   80          // max edges per row bin (binomial mean 16; P(deg>80)~0)

__device__ __half g_hh[NMAX * D_OUT];
__device__ float  g_w2[NMAX];
__device__ int    g_cnt[NMAX];
__device__ unsigned long long g_bins[(size_t)NMAX * CAP];

__device__ __forceinline__ unsigned long long fma2(
    unsigned long long a, unsigned long long b, unsigned long long c)
{
    unsigned long long d;
    asm("fma.rn.f32x2 %0, %1, %2, %3;" : "=l"(d) : "l"(a), "l"(b), "l"(c));
    return d;
}

__device__ __forceinline__ unsigned long long pack2(float x)
{
    unsigned long long d;
    asm("mov.b64 %0, {%1, %1};" : "=l"(d) : "f"(x));
    return d;
}

// ---------------------------------------------------------------------------
// Kernel A: h = relu(X @ W) in fp16 + w2 precompute. (R12-proven, unchanged)
// 256 threads, 256-row tile, thread = 8 rows x 4 cols.
// ---------------------------------------------------------------------------
__global__ __launch_bounds__(256, 2) void gemm_relu_kernel(
    const float* __restrict__ X, const float* __restrict__ W,
    const int* __restrict__ arrive, const float* __restrict__ dw2,
    const int* __restrict__ obs_ptr, int n)
{
    __shared__ float Xs[32 * 256];    // 32 KB
    __shared__ float Ws[128 * 32];    // 16 KB

    const int tid = threadIdx.x;
    const int rowbase = blockIdx.x * 256;

    {
        const int node = rowbase + tid;
        if (node < n) {
            const int obs = obs_ptr ? __ldg(obs_ptr) : 60;
            const int idx = 60 * obs - __ldg(arrive + node) - 1;
            g_w2[node] = __ldg(dw2 + idx);
        }
    }

    const float4* X4 = reinterpret_cast<const float4*>(X);
    const int lc = tid & 7;

    float4 pf[8];
    #pragma unroll
    for (int s = 0; s < 8; s++) {
        const int r = (s * 256 + tid) >> 3;
        float4 v = make_float4(0.f, 0.f, 0.f, 0.f);
        if (rowbase + r < n) v = X4[(size_t)(rowbase + r) * 32 + lc];
        pf[s] = v;
    }

    const float4* W4 = reinterpret_cast<const float4*>(W);
    float4* Ws4 = reinterpret_cast<float4*>(Ws);
    #pragma unroll
    for (int i = tid; i < 1024; i += 256) Ws4[i] = W4[i];

    const int rowgrp = tid >> 3;
    const int c0 = (tid & 7) * 4;
    const int b0 = rowgrp * 2;

    unsigned long long acc[4][4];
    #pragma unroll
    for (int rp = 0; rp < 4; rp++)
        #pragma unroll
        for (int j = 0; j < 4; j++) acc[rp][j] = 0ULL;

    #pragma unroll 1
    for (int chunk = 0; chunk < 4; chunk++) {
        #pragma unroll
        for (int s = 0; s < 8; s++) {
            const int r = (s * 256 + tid) >> 3;
            const int base = 4 * ((r >> 2) ^ lc) + (r & 3);
            Xs[(4 * lc + 0) * 256 + base] = pf[s].x;
            Xs[(4 * lc + 1) * 256 + base] = pf[s].y;
            Xs[(4 * lc + 2) * 256 + base] = pf[s].z;
            Xs[(4 * lc + 3) * 256 + base] = pf[s].w;
        }
        __syncthreads();

        if (chunk < 3) {
            #pragma unroll
            for (int s = 0; s < 8; s++) {
                const int r = (s * 256 + tid) >> 3;
                float4 v = make_float4(0.f, 0.f, 0.f, 0.f);
                if (rowbase + r < n)
                    v = X4[(size_t)(rowbase + r) * 32 + (chunk + 1) * 8 + lc];
                pf[s] = v;
            }
        }

        #pragma unroll 4
        for (int kl = 0; kl < 32; kl++) {
            const int m = kl >> 2;
            const ulonglong2 pa = *reinterpret_cast<const ulonglong2*>(
                &Xs[kl * 256 + (((b0)     ^ m) << 2)]);
            const ulonglong2 pb = *reinterpret_cast<const ulonglong2*>(
                &Xs[kl * 256 + (((b0 + 1) ^ m) << 2)]);

            const int kg = chunk * 32 + kl;
            const float4 w = *reinterpret_cast<const float4*>(&Ws[kg * 32 + c0]);
            const unsigned long long wp0 = pack2(w.x);
            const unsigned long long wp1 = pack2(w.y);
            const unsigned long long wp2 = pack2(w.z);
            const unsigned long long wp3 = pack2(w.w);

            acc[0][0] = fma2(pa.x, wp0, acc[0][0]);
            acc[0][1] = fma2(pa.x, wp1, acc[0][1]);
            acc[0][2] = fma2(pa.x, wp2, acc[0][2]);
            acc[0][3] = fma2(pa.x, wp3, acc[0][3]);
            acc[1][0] = fma2(pa.y, wp0, acc[1][0]);
            acc[1][1] = fma2(pa.y, wp1, acc[1][1]);
            acc[1][2] = fma2(pa.y, wp2, acc[1][2]);
            acc[1][3] = fma2(pa.y, wp3, acc[1][3]);
            acc[2][0] = fma2(pb.x, wp0, acc[2][0]);
            acc[2][1] = fma2(pb.x, wp1, acc[2][1]);
            acc[2][2] = fma2(pb.x, wp2, acc[2][2]);
            acc[2][3] = fma2(pb.x, wp3, acc[2][3]);
            acc[3][0] = fma2(pb.y, wp0, acc[3][0]);
            acc[3][1] = fma2(pb.y, wp1, acc[3][1]);
            acc[3][2] = fma2(pb.y, wp2, acc[3][2]);
            acc[3][3] = fma2(pb.y, wp3, acc[3][3]);
        }
        __syncthreads();
    }

    #pragma unroll
    for (int rp = 0; rp < 4; rp++) {
        float lo[4], hi[4];
        #pragma unroll
        for (int j = 0; j < 4; j++) {
            float l, h;
            asm("mov.b64 {%0, %1}, %2;" : "=f"(l), "=f"(h) : "l"(acc[rp][j]));
            lo[j] = fmaxf(l, 0.f);
            hi[j] = fmaxf(h, 0.f);
        }
        const int grl = rowbase + rowgrp * 8 + 2 * rp;
        if (grl < n) {
            const __half2 a = __floats2half2_rn(lo[0], lo[1]);
            const __half2 b = __floats2half2_rn(lo[2], lo[3]);
            uint2 u;
            u.x = *reinterpret_cast<const unsigned*>(&a);
            u.y = *reinterpret_cast<const unsigned*>(&b);
            *reinterpret_cast<uint2*>(&g_hh[grl * D_OUT + c0]) = u;
        }
        if (grl + 1 < n) {
            const __half2 a = __floats2half2_rn(hi[0], hi[1]);
            const __half2 b = __floats2half2_rn(hi[2], hi[3]);
            uint2 u;
            u.x = *reinterpret_cast<const unsigned*>(&a);
            u.y = *reinterpret_cast<const unsigned*>(&b);
            *reinterpret_cast<uint2*>(&g_hh[(grl + 1) * D_OUT + c0]) = u;
        }
    }
}

// ---------------------------------------------------------------------------
// Kernel B: bin edges — 8 edges/thread for doubled atomic MLP.
// All 8 independent ATOMGs issue before any dependent STG.
// ---------------------------------------------------------------------------
__global__ __launch_bounds__(256) void bin_kernel(
    const int* __restrict__ erow, const int* __restrict__ ecol,
    const int* __restrict__ etime, const float* __restrict__ dw1, int E)
{
    const int i = blockIdx.x * 256 + threadIdx.x;
    const int e0 = i * 8;
    if (e0 + 7 < E) {
        const int4 ra = reinterpret_cast<const int4*>(erow)[2 * i];
        const int4 rb = reinterpret_cast<const int4*>(erow)[2 * i + 1];
        const int4 ca = reinterpret_cast<const int4*>(ecol)[2 * i];
        const int4 cb = reinterpret_cast<const int4*>(ecol)[2 * i + 1];
        const int4 ta = reinterpret_cast<const int4*>(etime)[2 * i];
        const int4 tb = reinterpret_cast<const int4*>(etime)[2 * i + 1];

        unsigned long long pl[8];
        pl[0] = (unsigned)ca.x | ((unsigned long long)__float_as_uint(__ldg(dw1 + ta.x)) << 32);
        pl[1] = (unsigned)ca.y | ((unsigned long long)__float_as_uint(__ldg(dw1 + ta.y)) << 32);
        pl[2] = (unsigned)ca.z | ((unsigned long long)__float_as_uint(__ldg(dw1 + ta.z)) << 32);
        pl[3] = (unsigned)ca.w | ((unsigned long long)__float_as_uint(__ldg(dw1 + ta.w)) << 32);
        pl[4] = (unsigned)cb.x | ((unsigned long long)__float_as_uint(__ldg(dw1 + tb.x)) << 32);
        pl[5] = (unsigned)cb.y | ((unsigned long long)__float_as_uint(__ldg(dw1 + tb.y)) << 32);
        pl[6] = (unsigned)cb.z | ((unsigned long long)__float_as_uint(__ldg(dw1 + tb.z)) << 32);
        pl[7] = (unsigned)cb.w | ((unsigned long long)__float_as_uint(__ldg(dw1 + tb.w)) << 32);

        int p[8];
        p[0] = atomicAdd(&g_cnt[ra.x], 1);
        p[1] = atomicAdd(&g_cnt[ra.y], 1);
        p[2] = atomicAdd(&g_cnt[ra.z], 1);
        p[3] = atomicAdd(&g_cnt[ra.w], 1);
        p[4] = atomicAdd(&g_cnt[rb.x], 1);
        p[5] = atomicAdd(&g_cnt[rb.y], 1);
        p[6] = atomicAdd(&g_cnt[rb.z], 1);
        p[7] = atomicAdd(&g_cnt[rb.w], 1);

        if (p[0] < CAP) g_bins[(size_t)ra.x * CAP + p[0]] = pl[0];
        if (p[1] < CAP) g_bins[(size_t)ra.y * CAP + p[1]] = pl[1];
        if (p[2] < CAP) g_bins[(size_t)ra.z * CAP + p[2]] = pl[2];
        if (p[3] < CAP) g_bins[(size_t)ra.w * CAP + p[3]] = pl[3];
        if (p[4] < CAP) g_bins[(size_t)rb.x * CAP + p[4]] = pl[4];
        if (p[5] < CAP) g_bins[(size_t)rb.y * CAP + p[5]] = pl[5];
        if (p[6] < CAP) g_bins[(size_t)rb.z * CAP + p[6]] = pl[6];
        if (p[7] < CAP) g_bins[(size_t)rb.w * CAP + p[7]] = pl[7];
    } else if (e0 < E) {
        for (int e = e0; e < E; e++) {
            const int r = erow[e];
            const unsigned long long pl = (unsigned)ecol[e] |
                ((unsigned long long)__float_as_uint(__ldg(dw1 + etime[e])) << 32);
            const int p = atomicAdd(&g_cnt[r], 1);
            if (p < CAP) g_bins[(size_t)r * CAP + p] = pl;
        }
    }
}

// ---------------------------------------------------------------------------
// Kernel C: gather (fp16 h), no atomics. 8 lanes/row, 4-wide unroll.
// ---------------------------------------------------------------------------
__global__ __launch_bounds__(256) void gather_kernel(float* __restrict__ out, int n)
{
    const int gid = blockIdx.x * 256 + threadIdx.x;
    const int r = gid >> 3;
    const int p = gid & 7;
    if (r >= n) return;

    int deg = __ldg(&g_cnt[r]);
    if (deg > CAP) deg = CAP;
    const unsigned long long* bin = &g_bins[(size_t)r * CAP];

    float a0 = 0.f, a1 = 0.f, a2 = 0.f, a3 = 0.f;

    int i = 0;
    for (; i + 3 < deg; i += 4) {
        const unsigned long long pk0 = __ldg(&bin[i]);
        const unsigned long long pk1 = __ldg(&bin[i + 1]);
        const unsigned long long pk2 = __ldg(&bin[i + 2]);
        const unsigned long long pk3 = __ldg(&bin[i + 3]);
        const uint2 u0 = *reinterpret_cast<const uint2*>(
            &g_hh[(unsigned)pk0 * D_OUT + p * 4]);
        const uint2 u1 = *reinterpret_cast<const uint2*>(
            &g_hh[(unsigned)pk1 * D_OUT + p * 4]);
        const uint2 u2 = *reinterpret_cast<const uint2*>(
            &g_hh[(unsigned)pk2 * D_OUT + p * 4]);
        const uint2 u3 = *reinterpret_cast<const uint2*>(
            &g_hh[(unsigned)pk3 * D_OUT + p * 4]);
        const float d0 = __uint_as_float((unsigned)(pk0 >> 32));
        const float d1 = __uint_as_float((unsigned)(pk1 >> 32));
        const float d2 = __uint_as_float((unsigned)(pk2 >> 32));
        const float d3 = __uint_as_float((unsigned)(pk3 >> 32));
        {
            const float2 f01 = __half22float2(*reinterpret_cast<const __half2*>(&u0.x));
            const float2 f23 = __half22float2(*reinterpret_cast<const __half2*>(&u0.y));
            a0 = fmaf(d0, f01.x, a0); a1 = fmaf(d0, f01.y, a1);
            a2 = fmaf(d0, f23.x, a2); a3 = fmaf(d0, f23.y, a3);
        }
        {
            const float2 f01 = __half22float2(*reinterpret_cast<const __half2*>(&u1.x));
            const float2 f23 = __half22float2(*reinterpret_cast<const __half2*>(&u1.y));
            a0 = fmaf(d1, f01.x, a0); a1 = fmaf(d1, f01.y, a1);
            a2 = fmaf(d1, f23.x, a2); a3 = fmaf(d1, f23.y, a3);
        }
        {
            const float2 f01 = __half22float2(*reinterpret_cast<const __half2*>(&u2.x));
            const float2 f23 = __half22float2(*reinterpret_cast<const __half2*>(&u2.y));
            a0 = fmaf(d2, f01.x, a0); a1 = fmaf(d2, f01.y, a1);
            a2 = fmaf(d2, f23.x, a2); a3 = fmaf(d2, f23.y, a3);
        }
        {
            const float2 f01 = __half22float2(*reinterpret_cast<const __half2*>(&u3.x));
            const float2 f23 = __half22float2(*reinterpret_cast<const __half2*>(&u3.y));
            a0 = fmaf(d3, f01.x, a0); a1 = fmaf(d3, f01.y, a1);
            a2 = fmaf(d3, f23.x, a2); a3 = fmaf(d3, f23.y, a3);
        }
    }
    for (; i < deg; i++) {
        const unsigned long long pk = __ldg(&bin[i]);
        const float d = __uint_as_float((unsigned)(pk >> 32));
        const uint2 u = *reinterpret_cast<const uint2*>(
            &g_hh[(unsigned)pk * D_OUT + p * 4]);
        const float2 f01 = __half22float2(*reinterpret_cast<const __half2*>(&u.x));
        const float2 f23 = __half22float2(*reinterpret_cast<const __half2*>(&u.y));
        a0 = fmaf(d, f01.x, a0); a1 = fmaf(d, f01.y, a1);
        a2 = fmaf(d, f23.x, a2); a3 = fmaf(d, f23.y, a3);
    }

    const float w = __ldg(&g_w2[r]);
    *reinterpret_cast<float4*>(&out[r * D_OUT + p * 4]) =
        make_float4(a0 * w, a1 * w, a2 * w, a3 * w);
}

// ---------------------------------------------------------------------------
extern "C" void kernel_launch(void* const* d_in, const int* in_sizes, int n_in,
                              void* d_out, int out_size)
{
    const float* X    = (const float*)d_in[0];
    const float* W    = (const float*)d_in[1];
    const float* dw1  = (const float*)d_in[2];
    const float* dw2  = (const float*)d_in[3];
    const int*  erow  = (const int*)d_in[4];
    const int*  ecol  = (const int*)d_in[5];
    const int*  etime = (const int*)d_in[6];
    const int*  arrive= (const int*)d_in[7];
    const int*  obs_p = (n_in > 8) ? (const int*)d_in[8] : nullptr;

    const int n = in_sizes[7];
    const int E = in_sizes[4];

    void* cnt_ptr = nullptr;
    cudaGetSymbolAddress(&cnt_ptr, g_cnt);
    cudaMemsetAsync(cnt_ptr, 0, (size_t)n * sizeof(int));

    bin_kernel<<<(E / 8 + 255) / 256 + 1, 256>>>(erow, ecol, etime, dw1, E);
    gemm_relu_kernel<<<(n + 255) / 256, 256>>>(X, W, arrive, dw2, obs_p, n);
    gather_kernel<<<(n * 8 + 255) / 256, 256>>>((float*)d_out, n);
}